// round 1
// baseline (speedup 1.0000x reference)
#include <cuda_runtime.h>

// Problem constants (fixed shapes per reference setup_inputs)
#define BB 16
#define TT 288
#define NN 4096
#define FF 2
#define HH 10
#define RR 16
#define TCHUNKS 4
#define TPC (TT / TCHUNKS)   // 72

// Scratch: per-(tchunk, b, n) partial valid-sums and valid-counts.
// Written fully every launch (no accumulation) -> graph-replay safe, no zeroing.
__device__ float g_sum[TCHUNKS][BB][NN];
__device__ float g_cnt[TCHUNKS][BB][NN];
__device__ float g_gmean;

// ---------------------------------------------------------------------------
// Kernel 1: the only heavy pass. Reads all 151MB once (float4, streaming),
// produces per-(b,n) partial sums/counts of valid (x != -1) feature-0 values.
// grid = (NN/512, BB, TCHUNKS), block = 256. Each thread owns 2 adjacent n.
// ---------------------------------------------------------------------------
__global__ void __launch_bounds__(256) k1_partial_sums(const float4* __restrict__ data) {
    const int tid = threadIdx.x;
    const int b   = blockIdx.y;
    const int tc  = blockIdx.z;
    const int q   = blockIdx.x * 256 + tid;   // float4 column index [0, NN/2)
    const int n0  = q * 2;

    const float4* __restrict__ p =
        data + (size_t)(b * TT + tc * TPC) * (NN / 2) + q;

    float s0 = 0.f, s1 = 0.f, c0 = 0.f, c1 = 0.f;
    #pragma unroll 4
    for (int t = 0; t < TPC; ++t) {
        float4 v = __ldcs(p);
        p += NN / 2;
        // feature 0 of node n0 is v.x, of node n0+1 is v.z
        if (v.x != -1.0f) { s0 += v.x; c0 += 1.0f; }
        if (v.z != -1.0f) { s1 += v.z; c1 += 1.0f; }
    }
    g_sum[tc][b][n0]     = s0;
    g_sum[tc][b][n0 + 1] = s1;
    g_cnt[tc][b][n0]     = c0;
    g_cnt[tc][b][n0 + 1] = c1;
}

// ---------------------------------------------------------------------------
// Kernel 2: reduce all partials -> global mean of valid entries. One block.
// ---------------------------------------------------------------------------
__global__ void __launch_bounds__(1024) k2_gmean() {
    const float* __restrict__ s = &g_sum[0][0][0];
    const float* __restrict__ c = &g_cnt[0][0][0];
    const int total = TCHUNKS * BB * NN;  // 262144

    float ls = 0.f, lc = 0.f;
    for (int i = threadIdx.x; i < total; i += 1024) {
        ls += s[i];
        lc += c[i];
    }
    __shared__ float sh_s[1024];
    __shared__ float sh_c[1024];
    sh_s[threadIdx.x] = ls;
    sh_c[threadIdx.x] = lc;
    __syncthreads();
    #pragma unroll
    for (int o = 512; o > 0; o >>= 1) {
        if (threadIdx.x < o) {
            sh_s[threadIdx.x] += sh_s[threadIdx.x + o];
            sh_c[threadIdx.x] += sh_c[threadIdx.x + o];
        }
        __syncthreads();
    }
    if (threadIdx.x == 0)
        g_gmean = sh_s[0] / fmaxf(sh_c[0], 1.0f);
}

// ---------------------------------------------------------------------------
// Kernel 3: per-(b,n) imputed time-mean -> pred_speed tiled over H=10,
// plus per-region mean -> regional tiled over H=10.
// Output layout: [pred_speed (BB*HH*NN)] then [regional (BB*HH*RR)].
// grid = BB blocks, 1024 threads.
// ---------------------------------------------------------------------------
__global__ void __launch_bounds__(1024) k3_outputs(const int* __restrict__ cid,
                                                   float* __restrict__ out) {
    const int b   = blockIdx.x;
    const int tid = threadIdx.x;

    __shared__ float rs[RR];
    __shared__ float rc[RR];
    if (tid < RR) { rs[tid] = 0.f; rc[tid] = 0.f; }
    __syncthreads();

    const float gm   = g_gmean;
    const float invT = 1.0f / (float)TT;

    for (int n = tid; n < NN; n += 1024) {
        float s = g_sum[0][b][n] + g_sum[1][b][n] + g_sum[2][b][n] + g_sum[3][b][n];
        float c = g_cnt[0][b][n] + g_cnt[1][b][n] + g_cnt[2][b][n] + g_cnt[3][b][n];
        float mean = (s + ((float)TT - c) * gm) * invT;

        #pragma unroll
        for (int h = 0; h < HH; ++h)
            out[((size_t)b * HH + h) * NN + n] = mean;

        int r = cid[n];
        atomicAdd(&rs[r], mean);
        atomicAdd(&rc[r], 1.0f);
    }
    __syncthreads();

    if (tid < RR) {
        float v = rs[tid] / fmaxf(rc[tid], 1.0f);
        float* __restrict__ ro = out + (size_t)BB * HH * NN;
        #pragma unroll
        for (int h = 0; h < HH; ++h)
            ro[((size_t)b * HH + h) * RR + tid] = v;
    }
}

// ---------------------------------------------------------------------------
extern "C" void kernel_launch(void* const* d_in, const int* in_sizes, int n_in,
                              void* d_out, int out_size) {
    const float4* data = (const float4*)d_in[0];
    const int*    cid  = (const int*)d_in[1];
    float*        out  = (float*)d_out;

    dim3 g1(NN / 512, BB, TCHUNKS);   // (8, 16, 4) = 512 blocks
    k1_partial_sums<<<g1, 256>>>(data);
    k2_gmean<<<1, 1024>>>();
    k3_outputs<<<BB, 1024>>>(cid, out);
}

// round 2
// speedup vs baseline: 1.3392x; 1.3392x over previous
#include <cuda_runtime.h>

// Problem constants (fixed shapes per reference setup_inputs)
#define BB 16
#define TT 288
#define NN 4096
#define HH 10
#define RR 16
#define TCHUNKS 8
#define TPC (TT / TCHUNKS)        // 36
#define XBLK (NN / 512)           // 8 blocks along n (256 thr * 2 nodes)
#define NBLKS1 (XBLK * BB * TCHUNKS)  // 1024 k1 blocks
#define K3X 16                    // n-chunks in k3 (256 nodes each)

// Scratch (written fully every replay before being read -> graph-safe)
__device__ float g_sum[TCHUNKS][BB][NN];   // per-(tc,b,n) valid sums
__device__ float g_cnt[TCHUNKS][BB][NN];   // per-(tc,b,n) valid counts
__device__ float g_blk_s[NBLKS1];          // per-k1-block total sum
__device__ float g_blk_c[NBLKS1];          // per-k1-block total count
__device__ float g_gmean;
__device__ float g_rcnt[RR];               // nodes per region
__device__ float g_regp[BB][K3X][RR];      // per-(b, n-chunk) regional partial sums

// ---------------------------------------------------------------------------
// Kernel 1: the single heavy pass over 151MB. float4 streaming loads.
// grid = (XBLK, BB, TCHUNKS) = (8,16,8) = 1024 blocks, block = 256.
// Each thread owns 2 adjacent nodes over TPC=36 timesteps.
// Also block-reduces (sum,cnt) so the gmean pass reads only 8KB.
// ---------------------------------------------------------------------------
__global__ void __launch_bounds__(256) k1_partial_sums(const float4* __restrict__ data) {
    const int tid = threadIdx.x;
    const int b   = blockIdx.y;
    const int tc  = blockIdx.z;
    const int q   = blockIdx.x * 256 + tid;   // float4 column in [0, NN/2)
    const int n0  = q * 2;

    const float4* __restrict__ p =
        data + (size_t)(b * TT + tc * TPC) * (NN / 2) + q;

    float s0 = 0.f, s1 = 0.f, c0 = 0.f, c1 = 0.f;
    #pragma unroll 6
    for (int t = 0; t < TPC; ++t) {
        float4 v = __ldcs(p);
        p += NN / 2;
        if (v.x != -1.0f) { s0 += v.x; c0 += 1.0f; }
        if (v.z != -1.0f) { s1 += v.z; c1 += 1.0f; }
    }
    g_sum[tc][b][n0]     = s0;
    g_sum[tc][b][n0 + 1] = s1;
    g_cnt[tc][b][n0]     = c0;
    g_cnt[tc][b][n0 + 1] = c1;

    // Block reduction of total sum / count
    float s = s0 + s1;
    float c = c0 + c1;
    #pragma unroll
    for (int o = 16; o > 0; o >>= 1) {
        s += __shfl_down_sync(0xffffffffu, s, o);
        c += __shfl_down_sync(0xffffffffu, c, o);
    }
    __shared__ float sh_s[8], sh_c[8];
    const int wid = tid >> 5, lane = tid & 31;
    if (lane == 0) { sh_s[wid] = s; sh_c[wid] = c; }
    __syncthreads();
    if (wid == 0) {
        s = (lane < 8) ? sh_s[lane] : 0.f;
        c = (lane < 8) ? sh_c[lane] : 0.f;
        #pragma unroll
        for (int o = 4; o > 0; o >>= 1) {
            s += __shfl_down_sync(0xffffffffu, s, o);
            c += __shfl_down_sync(0xffffffffu, c, o);
        }
        if (lane == 0) {
            const int bid = (blockIdx.z * BB + blockIdx.y) * XBLK + blockIdx.x;
            g_blk_s[bid] = s;
            g_blk_c[bid] = c;
        }
    }
}

// ---------------------------------------------------------------------------
// Kernel 2: gmean from 1024 block partials + region node counts from cid.
// 1 block, 1024 threads, ~24KB of reads total.
// ---------------------------------------------------------------------------
__global__ void __launch_bounds__(1024) k2_gmean(const int* __restrict__ cid) {
    const int tid = threadIdx.x;

    __shared__ float rc[RR];
    if (tid < RR) rc[tid] = 0.f;
    __syncthreads();

    // region counts (4096 ints, 4 per thread)
    #pragma unroll
    for (int i = tid; i < NN; i += 1024)
        atomicAdd(&rc[cid[i]], 1.0f);

    float s = g_blk_s[tid];
    float c = g_blk_c[tid];
    #pragma unroll
    for (int o = 16; o > 0; o >>= 1) {
        s += __shfl_down_sync(0xffffffffu, s, o);
        c += __shfl_down_sync(0xffffffffu, c, o);
    }
    __shared__ float sh_s[32], sh_c[32];
    const int wid = tid >> 5, lane = tid & 31;
    if (lane == 0) { sh_s[wid] = s; sh_c[wid] = c; }
    __syncthreads();
    if (wid == 0) {
        s = sh_s[lane];
        c = sh_c[lane];
        #pragma unroll
        for (int o = 16; o > 0; o >>= 1) {
            s += __shfl_down_sync(0xffffffffu, s, o);
            c += __shfl_down_sync(0xffffffffu, c, o);
        }
        if (lane == 0) g_gmean = s / fmaxf(c, 1.0f);
    }
    if (tid < RR) g_rcnt[tid] = rc[tid];
}

// ---------------------------------------------------------------------------
// Kernel 3: per-(b,n) imputed time-mean -> pred_speed (tiled H=10) +
// per-(b,nchunk) regional partial sums.
// grid = (K3X, BB) = 256 blocks, block = 256, one node per thread.
// ---------------------------------------------------------------------------
__global__ void __launch_bounds__(256) k3_pred(const int* __restrict__ cid,
                                               float* __restrict__ out) {
    const int b   = blockIdx.y;
    const int n   = blockIdx.x * 256 + threadIdx.x;
    const int tid = threadIdx.x;

    __shared__ float rs[RR];
    if (tid < RR) rs[tid] = 0.f;
    __syncthreads();

    const float gm   = g_gmean;
    const float invT = 1.0f / (float)TT;

    float s = 0.f, c = 0.f;
    #pragma unroll
    for (int tc = 0; tc < TCHUNKS; ++tc) {
        s += g_sum[tc][b][n];
        c += g_cnt[tc][b][n];
    }
    const float mean = (s + ((float)TT - c) * gm) * invT;

    #pragma unroll
    for (int h = 0; h < HH; ++h)
        out[((size_t)b * HH + h) * NN + n] = mean;

    atomicAdd(&rs[cid[n]], mean);
    __syncthreads();

    if (tid < RR)
        g_regp[b][blockIdx.x][tid] = rs[tid];
}

// ---------------------------------------------------------------------------
// Kernel 4: regional output. 1 block of 256 threads: tid -> (b, r).
// regional[b][h][r] = (sum over nchunks of g_regp[b][x][r]) / rcnt[r].
// ---------------------------------------------------------------------------
__global__ void __launch_bounds__(256) k4_regional(float* __restrict__ out) {
    const int b = threadIdx.x >> 4;   // /16
    const int r = threadIdx.x & 15;

    float s = 0.f;
    #pragma unroll
    for (int x = 0; x < K3X; ++x)
        s += g_regp[b][x][r];
    const float v = s / fmaxf(g_rcnt[r], 1.0f);

    float* __restrict__ ro = out + (size_t)BB * HH * NN;
    #pragma unroll
    for (int h = 0; h < HH; ++h)
        ro[((size_t)b * HH + h) * RR + r] = v;
}

// ---------------------------------------------------------------------------
extern "C" void kernel_launch(void* const* d_in, const int* in_sizes, int n_in,
                              void* d_out, int out_size) {
    const float4* data = (const float4*)d_in[0];
    const int*    cid  = (const int*)d_in[1];
    float*        out  = (float*)d_out;

    dim3 g1(XBLK, BB, TCHUNKS);   // (8, 16, 8) = 1024 blocks
    k1_partial_sums<<<g1, 256>>>(data);
    k2_gmean<<<1, 1024>>>(cid);
    dim3 g3(K3X, BB);             // 256 blocks
    k3_pred<<<g3, 256>>>(cid, out);
    k4_regional<<<1, 256>>>(out);
}